// round 13
// baseline (speedup 1.0000x reference)
#include <cuda_runtime.h>

// ---------------------------------------------------------------------------
// SymmetricContraction: out[b,c,m] = cubic polynomial in A[b,c,0..8]
// Launch 1 (prep):  S[c][t][m] = sum_k Usym[t][m][k] * w_k[c]  (g_S)
// Launch 2 (main):  fused, f32x2, NBT=4 nodes/thread.
//   128 thr = 4 warps = 2 channels x 2 node-halves; 256 nodes/block.
//   2 S-tables + A tile staged in smem; each table-row LDS feeds 4 node-pairs.
// ---------------------------------------------------------------------------

#define NC 128
#define NB 2048
#define NI 9
#define NT 219
#define ROWP 12
#define TBLW (NT * ROWP)            // 2628 floats per channel table
#define CPB 2                       // channels per block
#define NBT 4                       // nodes per thread
#define BLKT 128                    // threads per main block
#define NPB 256                     // nodes per block (2 halves * 32 * 4)
#define TS2 (CPB * NI + 1)          // 19, odd -> conflict-free
#define SMEM_FLOATS (CPB * TBLW + NPB * TS2)   // 5256 + 4864 = 10120
#define SMEM_BYTES (SMEM_FLOATS * 4)           // 40480 (< 48KB default)

#define NJOBS (NT * 9)
#define RPB 2
#define PREP_BLOCKS ((NJOBS + RPB - 1) / RPB)  // 986

static __device__ float g_S[NC * TBLW];

typedef unsigned long long u64;

__device__ __forceinline__ u64 dup2(float x) {
    u64 r; unsigned xi = __float_as_uint(x);
    asm("mov.b64 %0, {%1, %1};" : "=l"(r) : "r"(xi));
    return r;
}
__device__ __forceinline__ u64 fma2(u64 a, u64 b, u64 c) {
    u64 r;
    asm("fma.rn.f32x2 %0, %1, %2, %3;" : "=l"(r) : "l"(a), "l"(b), "l"(c));
    return r;
}
__device__ __forceinline__ void unpack2(u64 v, float& lo, float& hi) {
    unsigned l_, h_;
    asm("mov.b64 {%0, %1}, %2;" : "=r"(l_), "=r"(h_) : "l"(v));
    lo = __uint_as_float(l_); hi = __uint_as_float(h_);
}

// ---------------------------------------------------------------------------
// Launch 1: prep (verified R11/R12 logic, unchanged)
// ---------------------------------------------------------------------------
__global__ __launch_bounds__(256) void prep_kernel(
    const float* __restrict__ Us1, const float* __restrict__ Up1, const float* __restrict__ Ud1,
    const float* __restrict__ Us2, const float* __restrict__ Up2, const float* __restrict__ Ud2,
    const float* __restrict__ Us3, const float* __restrict__ Up3, const float* __restrict__ Ud3,
    const float* __restrict__ ws1, const float* __restrict__ ws2, const float* __restrict__ ws3,
    const float* __restrict__ wp1, const float* __restrict__ wp2, const float* __restrict__ wp3,
    const float* __restrict__ wd1, const float* __restrict__ wd2, const float* __restrict__ wd3)
{
    __shared__ float sU[RPB][10];
    int r0 = blockIdx.x * RPB;
    int tid = threadIdx.x;

    if (tid < RPB * 10) {
        int rl = tid / 10, k = tid % 10;
        int r = r0 + rl;
        float usym = 0.f;
        if (r < NJOBS) {
            int t = r / 9, m = r - t * 9;
            if (t < 9) {
                if (k == 0) {
                    int i = t;
                    if (m == 0)      usym = Us1[i];
                    else if (m < 4)  usym = Up1[(m - 1) * 9 + i];
                    else             usym = Ud1[(m - 4) * 9 + i];
                }
            } else if (t < 54) {
                int tp = t - 9;
                int rem = tp, i = 0, j = 0;
                for (i = 0; i < 9; i++) { int cnt = 9 - i; if (rem < cnt) { j = i + rem; break; } rem -= cnt; }
                float inv = (i == j) ? 0.5f : 1.0f;
                int K; const float* U; int mm;
                if (m == 0)      { K = 2; U = Us2; mm = 0; }
                else if (m < 4)  { K = 3; U = Up2; mm = m - 1; }
                else             { K = 4; U = Ud2; mm = m - 4; }
                if (k < K)
                    usym = (U[((mm * 9 + i) * 9 + j) * K + k] +
                            U[((mm * 9 + j) * 9 + i) * K + k]) * inv;
            } else {
                int tp = t - 54;
                int rem = tp, i = 0, j = 0, l = 0;
                for (i = 0; i < 9; i++) { int cnt = (9 - i) * (10 - i) / 2; if (rem < cnt) break; rem -= cnt; }
                for (j = i; j < 9; j++) { int cnt = 9 - j; if (rem < cnt) { l = j + rem; break; } rem -= cnt; }
                float inv;
                if (i == j && j == l)                 inv = 1.0f / 6.0f;
                else if (i == j || j == l || i == l)  inv = 0.5f;
                else                                  inv = 1.0f;
                int K; const float* U; int mm;
                if (m == 0)      { K = 5;  U = Us3; mm = 0; }
                else if (m < 4)  { K = 8;  U = Up3; mm = m - 1; }
                else             { K = 10; U = Ud3; mm = m - 4; }
                if (k < K) {
                    int P0[6] = { i,i,j,j,l,l }, P1[6] = { j,l,i,l,i,j }, P2[6] = { l,j,l,i,j,i };
                    float s = 0.f;
#pragma unroll
                    for (int p = 0; p < 6; p++)
                        s += U[(((mm * 9 + P0[p]) * 9 + P1[p]) * 9 + P2[p]) * K + k];
                    usym = s * inv;
                }
            }
        }
        sU[rl][k] = usym;
    }
    __syncthreads();

    {
        int rl = tid >> 7;
        int c  = tid & 127;
        int r = r0 + rl;
        if (r >= NJOBS) return;
        int t = r / 9, m = r - t * 9;

        const float* w; int K;
        if (t < 9) {
            K = 1;
            w = (m == 0) ? ws1 : (m < 4) ? wp1 : wd1;
        } else if (t < 54) {
            if (m == 0)      { K = 2; w = ws2; }
            else if (m < 4)  { K = 3; w = wp2; }
            else             { K = 4; w = wd2; }
        } else {
            if (m == 0)      { K = 5;  w = ws3; }
            else if (m < 4)  { K = 8;  w = wp3; }
            else             { K = 10; w = wd3; }
        }

        float s = 0.f;
        for (int k = 0; k < K; k++)
            s = fmaf(sU[rl][k], w[k * NC + c], s);

        float* dst = g_S + c * TBLW + t * ROWP;
        dst[m] = s;
        if (m < 3) dst[9 + m] = 0.f;   // row[9] pad is load-bearing for f32x2
    }
}

// ---------------------------------------------------------------------------
// Launch 2: fused main, NBT=4
// ---------------------------------------------------------------------------
__device__ __forceinline__ void fmarow4(u64 acc[NBT][5],
                                        const float* __restrict__ row,
                                        const float mono[NBT])
{
    ulonglong2 ra = *reinterpret_cast<const ulonglong2*>(row);       // (r0,r1)(r2,r3)
    ulonglong2 rb = *reinterpret_cast<const ulonglong2*>(row + 4);   // (r4,r5)(r6,r7)
    u64 rc = *reinterpret_cast<const u64*>(row + 8);                 // (r8, pad)
#pragma unroll
    for (int n = 0; n < NBT; n++) {
        u64 d = dup2(mono[n]);
        acc[n][0] = fma2(ra.x, d, acc[n][0]);
        acc[n][1] = fma2(ra.y, d, acc[n][1]);
        acc[n][2] = fma2(rb.x, d, acc[n][2]);
        acc[n][3] = fma2(rb.y, d, acc[n][3]);
        acc[n][4] = fma2(rc,   d, acc[n][4]);
    }
}

__global__ __launch_bounds__(BLKT) void sc_main_kernel(
    const float* __restrict__ A, float* __restrict__ out)
{
    __shared__ __align__(16) float smem[SMEM_FLOATS];
    float* sT = smem;                    // [CPB][TBLW]
    float* sA = smem + CPB * TBLW;       // [NPB][TS2], reused for output

    int c0 = blockIdx.x * CPB;
    int b0 = blockIdx.y * NPB;
    int tid = threadIdx.x;
    int w = tid >> 5, lane = tid & 31;
    int ch = w & 1;                      // channel within block
    int half = w >> 1;                   // node half (0/1)

    // ---- fill tables: flat float4 copy (deep MLP)
    {
        const float4* src4 = reinterpret_cast<const float4*>(g_S + c0 * TBLW);
        float4* dst4 = reinterpret_cast<float4*>(sT);
#pragma unroll 4
        for (int v = tid; v < (CPB * TBLW) / 4; v += BLKT)
            dst4[v] = src4[v];
    }

    // ---- fill A tile: 256 runs of 18 contiguous floats
#pragma unroll 4
    for (int v = tid; v < NPB * (CPB * NI); v += BLKT) {
        int b = v / (CPB * NI), q = v - b * (CPB * NI);
        sA[b * TS2 + q] = A[(b0 + b) * (NC * NI) + c0 * NI + q];
    }
    __syncthreads();

    // ---- per-thread a vectors (stride-19 LDS, conflict-free)
    int nb = half * 128 + lane;          // node base; nodes nb + 32n
    float a[NBT][9];
#pragma unroll
    for (int n = 0; n < NBT; n++) {
        const float* p = sA + (nb + 32 * n) * TS2 + ch * NI;
#pragma unroll
        for (int i = 0; i < 9; i++) a[n][i] = p[i];
    }
    __syncthreads();   // all tile reads complete before epilogue overwrite

    const float* tbl = sT + ch * TBLW;

    u64 acc[NBT][5];
#pragma unroll
    for (int n = 0; n < NBT; n++)
#pragma unroll
        for (int q = 0; q < 5; q++) acc[n][q] = 0ull;

    // ---- degree 1
#pragma unroll
    for (int i = 0; i < 9; i++) {
        float mono[NBT];
#pragma unroll
        for (int n = 0; n < NBT; n++) mono[n] = a[n][i];
        fmarow4(acc, tbl + i * ROWP, mono);
    }

    // ---- degree 2 + 3
    int trow = 54;
#pragma unroll
    for (int i = 0; i < 9; i++) {
#pragma unroll
        for (int j = i; j < 9; j++) {
            int pidx = i * 9 - (i * (i - 1)) / 2 + (j - i);
            float pp[NBT];
#pragma unroll
            for (int n = 0; n < NBT; n++) pp[n] = a[n][i] * a[n][j];
            fmarow4(acc, tbl + (9 + pidx) * ROWP, pp);
#pragma unroll
            for (int l = j; l < 9; l++) {
                float mono[NBT];
#pragma unroll
                for (int n = 0; n < NBT; n++) mono[n] = pp[n] * a[n][l];
                fmarow4(acc, tbl + trow * ROWP, mono);
                trow++;
            }
        }
    }

    // ---- stage results into tile, then coalesced flush
#pragma unroll
    for (int n = 0; n < NBT; n++) {
        float* o = sA + (nb + 32 * n) * TS2 + ch * NI;
#pragma unroll
        for (int q = 0; q < 4; q++) {
            float lo, hi;
            unpack2(acc[n][q], lo, hi);
            o[2 * q] = lo; o[2 * q + 1] = hi;
        }
        float lo, hi;
        unpack2(acc[n][4], lo, hi);
        o[8] = lo;
    }
    __syncthreads();

#pragma unroll 4
    for (int v = tid; v < NPB * (CPB * NI); v += BLKT) {
        int b = v / (CPB * NI), q = v - b * (CPB * NI);
        out[(b0 + b) * (NC * NI) + c0 * NI + q] = sA[b * TS2 + q];
    }
}

// ---------------------------------------------------------------------------
// Launch
// ---------------------------------------------------------------------------
extern "C" void kernel_launch(void* const* d_in, const int* in_sizes, int n_in,
                              void* d_out, int out_size)
{
    const float* A = nullptr;
    const float* U[3][3] = {};
    const float* W[3][3] = {};

    int typeorder[3] = { 0, 1, 2 };
    int to_n = 0;
    int w1_idx[3]; int w1_n = 0;

    for (int idx = 0; idx < n_in; idx++) {
        int s = in_sizes[idx];
        const float* p = (const float*)d_in[idx];
        switch (s) {
            case NB * NC * NI: A = p; break;
            case 9:     U[0][0] = p; break;
            case 162:   U[0][1] = p; break;
            case 3645:  U[0][2] = p; break;
            case 27:    U[1][0] = p; break;
            case 729:   U[1][1] = p; break;
            case 17496: U[1][2] = p; break;
            case 45:    U[2][0] = p; break;
            case 1620:  U[2][1] = p; break;
            case 36450: U[2][2] = p; break;
            case 256:   W[0][1] = p; if (to_n < 3) typeorder[to_n++] = 0; break;
            case 384:   W[1][1] = p; if (to_n < 3) typeorder[to_n++] = 1; break;
            case 512:   W[2][1] = p; if (to_n < 3) typeorder[to_n++] = 2; break;
            case 640:   W[0][2] = p; break;
            case 1024:  W[1][2] = p; break;
            case 1280:  W[2][2] = p; break;
            case 128:   if (w1_n < 3) w1_idx[w1_n++] = idx; break;
            default: break;
        }
    }
    for (int q = 0; q < 3 && q < w1_n; q++)
        W[typeorder[q]][0] = (const float*)d_in[w1_idx[q]];

    // Launch 1: prep
    prep_kernel<<<PREP_BLOCKS, 256>>>(
        U[0][0], U[1][0], U[2][0],
        U[0][1], U[1][1], U[2][1],
        U[0][2], U[1][2], U[2][2],
        W[0][0], W[0][1], W[0][2],
        W[1][0], W[1][1], W[1][2],
        W[2][0], W[2][1], W[2][2]);

    // Launch 2: fused main, NBT=4
    {
        dim3 grid(NC / CPB, NB / NPB);   // (64, 8) = 512 blocks
        sc_main_kernel<<<grid, BLKT>>>(A, (float*)d_out);
    }
}

// round 14
// speedup vs baseline: 1.1426x; 1.1426x over previous
#include <cuda_runtime.h>

// ---------------------------------------------------------------------------
// SymmetricContraction: out[b,c,m] = cubic polynomial in A[b,c,0..8]
// Launch 1 (prep):  S[c][t][m] = sum_k Usym[t][m][k] * w_k[c]  (g_S)
// Launch 2 (main):  R12 champion config (f32x2, NBT=2, CPB=4, 256 thr)
//   + __launch_bounds__(256, 4): cap 64 regs -> 4 blocks/SM = 32 warps.
// ---------------------------------------------------------------------------

#define NC 128
#define NB 2048
#define NI 9
#define NT 219
#define ROWP 12
#define TBLW (NT * ROWP)          // 2628 floats per channel table
#define CPB 4                     // channels per block
#define NPB 128                   // nodes per block
#define TS 37                     // tile row stride (odd)
#define SM_FLOATS (CPB * TBLW + NPB * TS)     // 10512 + 4736 = 15248
#define SMEM_BYTES (SM_FLOATS * 4)            // 60992

#define NJOBS (NT * 9)
#define RPB 2
#define PREP_BLOCKS ((NJOBS + RPB - 1) / RPB)  // 986

static __device__ float g_S[NC * TBLW];

typedef unsigned long long u64;

__device__ __forceinline__ u64 dup2(float x) {
    u64 r; unsigned xi = __float_as_uint(x);
    asm("mov.b64 %0, {%1, %1};" : "=l"(r) : "r"(xi));
    return r;
}
__device__ __forceinline__ u64 fma2(u64 a, u64 b, u64 c) {
    u64 r;
    asm("fma.rn.f32x2 %0, %1, %2, %3;" : "=l"(r) : "l"(a), "l"(b), "l"(c));
    return r;
}
__device__ __forceinline__ void unpack2(u64 v, float& lo, float& hi) {
    unsigned l_, h_;
    asm("mov.b64 {%0, %1}, %2;" : "=r"(l_), "=r"(h_) : "l"(v));
    lo = __uint_as_float(l_); hi = __uint_as_float(h_);
}

// ---------------------------------------------------------------------------
// Launch 1: prep (verified, unchanged)
// ---------------------------------------------------------------------------
__global__ __launch_bounds__(256) void prep_kernel(
    const float* __restrict__ Us1, const float* __restrict__ Up1, const float* __restrict__ Ud1,
    const float* __restrict__ Us2, const float* __restrict__ Up2, const float* __restrict__ Ud2,
    const float* __restrict__ Us3, const float* __restrict__ Up3, const float* __restrict__ Ud3,
    const float* __restrict__ ws1, const float* __restrict__ ws2, const float* __restrict__ ws3,
    const float* __restrict__ wp1, const float* __restrict__ wp2, const float* __restrict__ wp3,
    const float* __restrict__ wd1, const float* __restrict__ wd2, const float* __restrict__ wd3)
{
    __shared__ float sU[RPB][10];
    int r0 = blockIdx.x * RPB;
    int tid = threadIdx.x;

    if (tid < RPB * 10) {
        int rl = tid / 10, k = tid % 10;
        int r = r0 + rl;
        float usym = 0.f;
        if (r < NJOBS) {
            int t = r / 9, m = r - t * 9;
            if (t < 9) {
                if (k == 0) {
                    int i = t;
                    if (m == 0)      usym = Us1[i];
                    else if (m < 4)  usym = Up1[(m - 1) * 9 + i];
                    else             usym = Ud1[(m - 4) * 9 + i];
                }
            } else if (t < 54) {
                int tp = t - 9;
                int rem = tp, i = 0, j = 0;
                for (i = 0; i < 9; i++) { int cnt = 9 - i; if (rem < cnt) { j = i + rem; break; } rem -= cnt; }
                float inv = (i == j) ? 0.5f : 1.0f;
                int K; const float* U; int mm;
                if (m == 0)      { K = 2; U = Us2; mm = 0; }
                else if (m < 4)  { K = 3; U = Up2; mm = m - 1; }
                else             { K = 4; U = Ud2; mm = m - 4; }
                if (k < K)
                    usym = (U[((mm * 9 + i) * 9 + j) * K + k] +
                            U[((mm * 9 + j) * 9 + i) * K + k]) * inv;
            } else {
                int tp = t - 54;
                int rem = tp, i = 0, j = 0, l = 0;
                for (i = 0; i < 9; i++) { int cnt = (9 - i) * (10 - i) / 2; if (rem < cnt) break; rem -= cnt; }
                for (j = i; j < 9; j++) { int cnt = 9 - j; if (rem < cnt) { l = j + rem; break; } rem -= cnt; }
                float inv;
                if (i == j && j == l)                 inv = 1.0f / 6.0f;
                else if (i == j || j == l || i == l)  inv = 0.5f;
                else                                  inv = 1.0f;
                int K; const float* U; int mm;
                if (m == 0)      { K = 5;  U = Us3; mm = 0; }
                else if (m < 4)  { K = 8;  U = Up3; mm = m - 1; }
                else             { K = 10; U = Ud3; mm = m - 4; }
                if (k < K) {
                    int P0[6] = { i,i,j,j,l,l }, P1[6] = { j,l,i,l,i,j }, P2[6] = { l,j,l,i,j,i };
                    float s = 0.f;
#pragma unroll
                    for (int p = 0; p < 6; p++)
                        s += U[(((mm * 9 + P0[p]) * 9 + P1[p]) * 9 + P2[p]) * K + k];
                    usym = s * inv;
                }
            }
        }
        sU[rl][k] = usym;
    }
    __syncthreads();

    {
        int rl = tid >> 7;
        int c  = tid & 127;
        int r = r0 + rl;
        if (r >= NJOBS) return;
        int t = r / 9, m = r - t * 9;

        const float* w; int K;
        if (t < 9) {
            K = 1;
            w = (m == 0) ? ws1 : (m < 4) ? wp1 : wd1;
        } else if (t < 54) {
            if (m == 0)      { K = 2; w = ws2; }
            else if (m < 4)  { K = 3; w = wp2; }
            else             { K = 4; w = wd2; }
        } else {
            if (m == 0)      { K = 5;  w = ws3; }
            else if (m < 4)  { K = 8;  w = wp3; }
            else             { K = 10; w = wd3; }
        }

        float s = 0.f;
        for (int k = 0; k < K; k++)
            s = fmaf(sU[rl][k], w[k * NC + c], s);

        float* dst = g_S + c * TBLW + t * ROWP;
        dst[m] = s;
        if (m < 3) dst[9 + m] = 0.f;   // row[9] pad is load-bearing for f32x2
    }
}

// ---------------------------------------------------------------------------
// Launch 2: fused main (R12 config, occupancy-forced)
// ---------------------------------------------------------------------------
__device__ __forceinline__ void fmarow(u64 acc0[5], u64 acc1[5],
                                       const float* __restrict__ row,
                                       float m0, float m1)
{
    u64 d0 = dup2(m0), d1 = dup2(m1);
    ulonglong2 ra = *reinterpret_cast<const ulonglong2*>(row);       // (r0,r1)(r2,r3)
    ulonglong2 rb = *reinterpret_cast<const ulonglong2*>(row + 4);   // (r4,r5)(r6,r7)
    u64 rc = *reinterpret_cast<const u64*>(row + 8);                 // (r8, pad)
    acc0[0] = fma2(ra.x, d0, acc0[0]);  acc1[0] = fma2(ra.x, d1, acc1[0]);
    acc0[1] = fma2(ra.y, d0, acc0[1]);  acc1[1] = fma2(ra.y, d1, acc1[1]);
    acc0[2] = fma2(rb.x, d0, acc0[2]);  acc1[2] = fma2(rb.x, d1, acc1[2]);
    acc0[3] = fma2(rb.y, d0, acc0[3]);  acc1[3] = fma2(rb.y, d1, acc1[3]);
    acc0[4] = fma2(rc,   d0, acc0[4]);  acc1[4] = fma2(rc,   d1, acc1[4]);
}

__global__ __launch_bounds__(256, 4) void sc_main_kernel(
    const float* __restrict__ A, float* __restrict__ out)
{
    extern __shared__ __align__(16) float smem[];
    float* sT = smem;                    // [CPB][TBLW]
    float* sA = smem + CPB * TBLW;       // [NPB][TS], reused for output

    int c0 = blockIdx.x * CPB;
    int b0 = blockIdx.y * NPB;
    int tid = threadIdx.x;
    int w4 = (tid >> 5) & 3;             // channel within block
    int half = tid >> 7;                 // node half
    int lane = tid & 31;

    // ---- fill tables: flat float4 copy (deep MLP)
    {
        const float4* src4 = reinterpret_cast<const float4*>(g_S + c0 * TBLW);
        float4* dst4 = reinterpret_cast<float4*>(sT);
#pragma unroll 4
        for (int v = tid; v < (CPB * TBLW) / 4; v += 256)
            dst4[v] = src4[v];
    }

    // ---- fill A tile: 128 runs of 36 contiguous floats
#pragma unroll 4
    for (int v = tid; v < NPB * 36; v += 256) {
        int b = v / 36, q = v - b * 36;
        sA[b * TS + q] = A[(b0 + b) * (NC * NI) + c0 * NI + q];
    }
    __syncthreads();

    // ---- per-thread a vectors (stride-37 LDS, conflict-free)
    int row0 = half * 64 + lane;
    float a0[9], a1[9];
    {
        const float* p0 = sA + row0 * TS + w4 * NI;
        const float* p1 = sA + (row0 + 32) * TS + w4 * NI;
#pragma unroll
        for (int i = 0; i < 9; i++) { a0[i] = p0[i]; a1[i] = p1[i]; }
    }
    __syncthreads();   // tile reads complete before epilogue overwrite

    const float* tbl = sT + w4 * TBLW;

    u64 acc0[5], acc1[5];
#pragma unroll
    for (int q = 0; q < 5; q++) { acc0[q] = 0ull; acc1[q] = 0ull; }

    // ---- degree 1
#pragma unroll
    for (int i = 0; i < 9; i++)
        fmarow(acc0, acc1, tbl + i * ROWP, a0[i], a1[i]);

    // ---- degree 2 + 3
    int trow = 54;
#pragma unroll
    for (int i = 0; i < 9; i++) {
#pragma unroll
        for (int j = i; j < 9; j++) {
            int pidx = i * 9 - (i * (i - 1)) / 2 + (j - i);
            float p0 = a0[i] * a0[j];
            float p1 = a1[i] * a1[j];
            fmarow(acc0, acc1, tbl + (9 + pidx) * ROWP, p0, p1);
#pragma unroll
            for (int l = j; l < 9; l++) {
                fmarow(acc0, acc1, tbl + trow * ROWP, p0 * a0[l], p1 * a1[l]);
                trow++;
            }
        }
    }

    // ---- stage results into tile, then coalesced flush
    {
        float* o0 = sA + row0 * TS + w4 * NI;
        float* o1 = sA + (row0 + 32) * TS + w4 * NI;
#pragma unroll
        for (int q = 0; q < 4; q++) {
            float lo, hi;
            unpack2(acc0[q], lo, hi); o0[2 * q] = lo; o0[2 * q + 1] = hi;
            unpack2(acc1[q], lo, hi); o1[2 * q] = lo; o1[2 * q + 1] = hi;
        }
        float lo, hi;
        unpack2(acc0[4], lo, hi); o0[8] = lo;
        unpack2(acc1[4], lo, hi); o1[8] = lo;
    }
    __syncthreads();

#pragma unroll 4
    for (int v = tid; v < NPB * 36; v += 256) {
        int b = v / 36, q = v - b * 36;
        out[(b0 + b) * (NC * NI) + c0 * NI + q] = sA[b * TS + q];
    }
}

// ---------------------------------------------------------------------------
// Launch
// ---------------------------------------------------------------------------
extern "C" void kernel_launch(void* const* d_in, const int* in_sizes, int n_in,
                              void* d_out, int out_size)
{
    const float* A = nullptr;
    const float* U[3][3] = {};
    const float* W[3][3] = {};

    int typeorder[3] = { 0, 1, 2 };
    int to_n = 0;
    int w1_idx[3]; int w1_n = 0;

    for (int idx = 0; idx < n_in; idx++) {
        int s = in_sizes[idx];
        const float* p = (const float*)d_in[idx];
        switch (s) {
            case NB * NC * NI: A = p; break;
            case 9:     U[0][0] = p; break;
            case 162:   U[0][1] = p; break;
            case 3645:  U[0][2] = p; break;
            case 27:    U[1][0] = p; break;
            case 729:   U[1][1] = p; break;
            case 17496: U[1][2] = p; break;
            case 45:    U[2][0] = p; break;
            case 1620:  U[2][1] = p; break;
            case 36450: U[2][2] = p; break;
            case 256:   W[0][1] = p; if (to_n < 3) typeorder[to_n++] = 0; break;
            case 384:   W[1][1] = p; if (to_n < 3) typeorder[to_n++] = 1; break;
            case 512:   W[2][1] = p; if (to_n < 3) typeorder[to_n++] = 2; break;
            case 640:   W[0][2] = p; break;
            case 1024:  W[1][2] = p; break;
            case 1280:  W[2][2] = p; break;
            case 128:   if (w1_n < 3) w1_idx[w1_n++] = idx; break;
            default: break;
        }
    }
    for (int q = 0; q < 3 && q < w1_n; q++)
        W[typeorder[q]][0] = (const float*)d_in[w1_idx[q]];

    static bool attr_done = false;
    if (!attr_done) {
        cudaFuncSetAttribute(sc_main_kernel,
                             cudaFuncAttributeMaxDynamicSharedMemorySize, SMEM_BYTES);
        attr_done = true;
    }

    // Launch 1: prep
    prep_kernel<<<PREP_BLOCKS, 256>>>(
        U[0][0], U[1][0], U[2][0],
        U[0][1], U[1][1], U[2][1],
        U[0][2], U[1][2], U[2][2],
        W[0][0], W[0][1], W[0][2],
        W[1][0], W[1][1], W[1][2],
        W[2][0], W[2][1], W[2][2]);

    // Launch 2: fused main
    {
        dim3 grid(NC / CPB, NB / NPB);   // (32, 16)
        sc_main_kernel<<<grid, 256, SMEM_BYTES>>>(A, (float*)d_out);
    }
}

// round 15
// speedup vs baseline: 1.2122x; 1.0608x over previous
#include <cuda_runtime.h>

// ---------------------------------------------------------------------------
// SymmetricContraction: out[b,c,m] = cubic polynomial in A[b,c,0..8]
// Launch 1 (prep):  S[c][t][m] = sum_k Usym[t][m][k] * w_k[c]  (g_S)
// Launch 2 (main):  fused f32x2, NBT=2, CPB=2, NPB=256, 256 thr.
//   smem 40.5KB -> 4 blocks/SM (32 warps), vs 61KB/3 blocks in R12/R14.
//   8 warps = 2 channels x 4 node-quarters.
// ---------------------------------------------------------------------------

#define NC 128
#define NB 2048
#define NI 9
#define NT 219
#define ROWP 12
#define TBLW (NT * ROWP)          // 2628 floats per channel table
#define CPB 2                     // channels per block
#define NPB 256                   // nodes per block
#define TS 19                     // tile row stride (2*9+1, odd)
#define SM_FLOATS (CPB * TBLW + NPB * TS)     // 5256 + 4864 = 10120
#define SMEM_BYTES (SM_FLOATS * 4)            // 40480 (< 48KB default)

#define NJOBS (NT * 9)
#define RPB 2
#define PREP_BLOCKS ((NJOBS + RPB - 1) / RPB)  // 986

static __device__ float g_S[NC * TBLW];

typedef unsigned long long u64;

__device__ __forceinline__ u64 dup2(float x) {
    u64 r; unsigned xi = __float_as_uint(x);
    asm("mov.b64 %0, {%1, %1};" : "=l"(r) : "r"(xi));
    return r;
}
__device__ __forceinline__ u64 fma2(u64 a, u64 b, u64 c) {
    u64 r;
    asm("fma.rn.f32x2 %0, %1, %2, %3;" : "=l"(r) : "l"(a), "l"(b), "l"(c));
    return r;
}
__device__ __forceinline__ void unpack2(u64 v, float& lo, float& hi) {
    unsigned l_, h_;
    asm("mov.b64 {%0, %1}, %2;" : "=r"(l_), "=r"(h_) : "l"(v));
    lo = __uint_as_float(l_); hi = __uint_as_float(h_);
}

// ---------------------------------------------------------------------------
// Launch 1: prep (verified, unchanged)
// ---------------------------------------------------------------------------
__global__ __launch_bounds__(256) void prep_kernel(
    const float* __restrict__ Us1, const float* __restrict__ Up1, const float* __restrict__ Ud1,
    const float* __restrict__ Us2, const float* __restrict__ Up2, const float* __restrict__ Ud2,
    const float* __restrict__ Us3, const float* __restrict__ Up3, const float* __restrict__ Ud3,
    const float* __restrict__ ws1, const float* __restrict__ ws2, const float* __restrict__ ws3,
    const float* __restrict__ wp1, const float* __restrict__ wp2, const float* __restrict__ wp3,
    const float* __restrict__ wd1, const float* __restrict__ wd2, const float* __restrict__ wd3)
{
    __shared__ float sU[RPB][10];
    int r0 = blockIdx.x * RPB;
    int tid = threadIdx.x;

    if (tid < RPB * 10) {
        int rl = tid / 10, k = tid % 10;
        int r = r0 + rl;
        float usym = 0.f;
        if (r < NJOBS) {
            int t = r / 9, m = r - t * 9;
            if (t < 9) {
                if (k == 0) {
                    int i = t;
                    if (m == 0)      usym = Us1[i];
                    else if (m < 4)  usym = Up1[(m - 1) * 9 + i];
                    else             usym = Ud1[(m - 4) * 9 + i];
                }
            } else if (t < 54) {
                int tp = t - 9;
                int rem = tp, i = 0, j = 0;
                for (i = 0; i < 9; i++) { int cnt = 9 - i; if (rem < cnt) { j = i + rem; break; } rem -= cnt; }
                float inv = (i == j) ? 0.5f : 1.0f;
                int K; const float* U; int mm;
                if (m == 0)      { K = 2; U = Us2; mm = 0; }
                else if (m < 4)  { K = 3; U = Up2; mm = m - 1; }
                else             { K = 4; U = Ud2; mm = m - 4; }
                if (k < K)
                    usym = (U[((mm * 9 + i) * 9 + j) * K + k] +
                            U[((mm * 9 + j) * 9 + i) * K + k]) * inv;
            } else {
                int tp = t - 54;
                int rem = tp, i = 0, j = 0, l = 0;
                for (i = 0; i < 9; i++) { int cnt = (9 - i) * (10 - i) / 2; if (rem < cnt) break; rem -= cnt; }
                for (j = i; j < 9; j++) { int cnt = 9 - j; if (rem < cnt) { l = j + rem; break; } rem -= cnt; }
                float inv;
                if (i == j && j == l)                 inv = 1.0f / 6.0f;
                else if (i == j || j == l || i == l)  inv = 0.5f;
                else                                  inv = 1.0f;
                int K; const float* U; int mm;
                if (m == 0)      { K = 5;  U = Us3; mm = 0; }
                else if (m < 4)  { K = 8;  U = Up3; mm = m - 1; }
                else             { K = 10; U = Ud3; mm = m - 4; }
                if (k < K) {
                    int P0[6] = { i,i,j,j,l,l }, P1[6] = { j,l,i,l,i,j }, P2[6] = { l,j,l,i,j,i };
                    float s = 0.f;
#pragma unroll
                    for (int p = 0; p < 6; p++)
                        s += U[(((mm * 9 + P0[p]) * 9 + P1[p]) * 9 + P2[p]) * K + k];
                    usym = s * inv;
                }
            }
        }
        sU[rl][k] = usym;
    }
    __syncthreads();

    {
        int rl = tid >> 7;
        int c  = tid & 127;
        int r = r0 + rl;
        if (r >= NJOBS) return;
        int t = r / 9, m = r - t * 9;

        const float* w; int K;
        if (t < 9) {
            K = 1;
            w = (m == 0) ? ws1 : (m < 4) ? wp1 : wd1;
        } else if (t < 54) {
            if (m == 0)      { K = 2; w = ws2; }
            else if (m < 4)  { K = 3; w = wp2; }
            else             { K = 4; w = wd2; }
        } else {
            if (m == 0)      { K = 5;  w = ws3; }
            else if (m < 4)  { K = 8;  w = wp3; }
            else             { K = 10; w = wd3; }
        }

        float s = 0.f;
        for (int k = 0; k < K; k++)
            s = fmaf(sU[rl][k], w[k * NC + c], s);

        float* dst = g_S + c * TBLW + t * ROWP;
        dst[m] = s;
        if (m < 3) dst[9 + m] = 0.f;   // row[9] pad is load-bearing for f32x2
    }
}

// ---------------------------------------------------------------------------
// Launch 2: fused main (CPB=2, NPB=256 -> 40.5KB smem -> 4 blocks/SM)
// ---------------------------------------------------------------------------
__device__ __forceinline__ void fmarow(u64 acc0[5], u64 acc1[5],
                                       const float* __restrict__ row,
                                       float m0, float m1)
{
    u64 d0 = dup2(m0), d1 = dup2(m1);
    ulonglong2 ra = *reinterpret_cast<const ulonglong2*>(row);       // (r0,r1)(r2,r3)
    ulonglong2 rb = *reinterpret_cast<const ulonglong2*>(row + 4);   // (r4,r5)(r6,r7)
    u64 rc = *reinterpret_cast<const u64*>(row + 8);                 // (r8, pad)
    acc0[0] = fma2(ra.x, d0, acc0[0]);  acc1[0] = fma2(ra.x, d1, acc1[0]);
    acc0[1] = fma2(ra.y, d0, acc0[1]);  acc1[1] = fma2(ra.y, d1, acc1[1]);
    acc0[2] = fma2(rb.x, d0, acc0[2]);  acc1[2] = fma2(rb.x, d1, acc1[2]);
    acc0[3] = fma2(rb.y, d0, acc0[3]);  acc1[3] = fma2(rb.y, d1, acc1[3]);
    acc0[4] = fma2(rc,   d0, acc0[4]);  acc1[4] = fma2(rc,   d1, acc1[4]);
}

__global__ __launch_bounds__(256, 4) void sc_main_kernel(
    const float* __restrict__ A, float* __restrict__ out)
{
    __shared__ __align__(16) float smem[SM_FLOATS];
    float* sT = smem;                    // [CPB][TBLW]
    float* sA = smem + CPB * TBLW;       // [NPB][TS], reused for output

    int c0 = blockIdx.x * CPB;
    int b0 = blockIdx.y * NPB;
    int tid = threadIdx.x;
    int w = tid >> 5, lane = tid & 31;
    int ch = w & 1;                      // channel within block
    int quad = w >> 1;                   // node quarter (0..3)

    // ---- fill tables: flat float4 copy (deep MLP)
    {
        const float4* src4 = reinterpret_cast<const float4*>(g_S + c0 * TBLW);
        float4* dst4 = reinterpret_cast<float4*>(sT);
#pragma unroll 4
        for (int v = tid; v < (CPB * TBLW) / 4; v += 256)
            dst4[v] = src4[v];
    }

    // ---- fill A tile: 256 runs of 18 contiguous floats
#pragma unroll 4
    for (int v = tid; v < NPB * (CPB * NI); v += 256) {
        int b = v / (CPB * NI), q = v - b * (CPB * NI);
        sA[b * TS + q] = A[(b0 + b) * (NC * NI) + c0 * NI + q];
    }
    __syncthreads();

    // ---- per-thread a vectors (stride-19 LDS, conflict-free)
    int row0 = quad * 64 + lane;         // nodes row0 and row0+32
    float a0[9], a1[9];
    {
        const float* p0 = sA + row0 * TS + ch * NI;
        const float* p1 = sA + (row0 + 32) * TS + ch * NI;
#pragma unroll
        for (int i = 0; i < 9; i++) { a0[i] = p0[i]; a1[i] = p1[i]; }
    }
    __syncthreads();   // tile reads complete before epilogue overwrite

    const float* tbl = sT + ch * TBLW;

    u64 acc0[5], acc1[5];
#pragma unroll
    for (int q = 0; q < 5; q++) { acc0[q] = 0ull; acc1[q] = 0ull; }

    // ---- degree 1
#pragma unroll
    for (int i = 0; i < 9; i++)
        fmarow(acc0, acc1, tbl + i * ROWP, a0[i], a1[i]);

    // ---- degree 2 + 3
    int trow = 54;
#pragma unroll
    for (int i = 0; i < 9; i++) {
#pragma unroll
        for (int j = i; j < 9; j++) {
            int pidx = i * 9 - (i * (i - 1)) / 2 + (j - i);
            float p0 = a0[i] * a0[j];
            float p1 = a1[i] * a1[j];
            fmarow(acc0, acc1, tbl + (9 + pidx) * ROWP, p0, p1);
#pragma unroll
            for (int l = j; l < 9; l++) {
                fmarow(acc0, acc1, tbl + trow * ROWP, p0 * a0[l], p1 * a1[l]);
                trow++;
            }
        }
    }

    // ---- stage results into tile, then coalesced flush
    {
        float* o0 = sA + row0 * TS + ch * NI;
        float* o1 = sA + (row0 + 32) * TS + ch * NI;
#pragma unroll
        for (int q = 0; q < 4; q++) {
            float lo, hi;
            unpack2(acc0[q], lo, hi); o0[2 * q] = lo; o0[2 * q + 1] = hi;
            unpack2(acc1[q], lo, hi); o1[2 * q] = lo; o1[2 * q + 1] = hi;
        }
        float lo, hi;
        unpack2(acc0[4], lo, hi); o0[8] = lo;
        unpack2(acc1[4], lo, hi); o1[8] = lo;
    }
    __syncthreads();

#pragma unroll 4
    for (int v = tid; v < NPB * (CPB * NI); v += 256) {
        int b = v / (CPB * NI), q = v - b * (CPB * NI);
        out[(b0 + b) * (NC * NI) + c0 * NI + q] = sA[b * TS + q];
    }
}

// ---------------------------------------------------------------------------
// Launch
// ---------------------------------------------------------------------------
extern "C" void kernel_launch(void* const* d_in, const int* in_sizes, int n_in,
                              void* d_out, int out_size)
{
    const float* A = nullptr;
    const float* U[3][3] = {};
    const float* W[3][3] = {};

    int typeorder[3] = { 0, 1, 2 };
    int to_n = 0;
    int w1_idx[3]; int w1_n = 0;

    for (int idx = 0; idx < n_in; idx++) {
        int s = in_sizes[idx];
        const float* p = (const float*)d_in[idx];
        switch (s) {
            case NB * NC * NI: A = p; break;
            case 9:     U[0][0] = p; break;
            case 162:   U[0][1] = p; break;
            case 3645:  U[0][2] = p; break;
            case 27:    U[1][0] = p; break;
            case 729:   U[1][1] = p; break;
            case 17496: U[1][2] = p; break;
            case 45:    U[2][0] = p; break;
            case 1620:  U[2][1] = p; break;
            case 36450: U[2][2] = p; break;
            case 256:   W[0][1] = p; if (to_n < 3) typeorder[to_n++] = 0; break;
            case 384:   W[1][1] = p; if (to_n < 3) typeorder[to_n++] = 1; break;
            case 512:   W[2][1] = p; if (to_n < 3) typeorder[to_n++] = 2; break;
            case 640:   W[0][2] = p; break;
            case 1024:  W[1][2] = p; break;
            case 1280:  W[2][2] = p; break;
            case 128:   if (w1_n < 3) w1_idx[w1_n++] = idx; break;
            default: break;
        }
    }
    for (int q = 0; q < 3 && q < w1_n; q++)
        W[typeorder[q]][0] = (const float*)d_in[w1_idx[q]];

    // Launch 1: prep
    prep_kernel<<<PREP_BLOCKS, 256>>>(
        U[0][0], U[1][0], U[2][0],
        U[0][1], U[1][1], U[2][1],
        U[0][2], U[1][2], U[2][2],
        W[0][0], W[0][1], W[0][2],
        W[1][0], W[1][1], W[1][2],
        W[2][0], W[2][1], W[2][2]);

    // Launch 2: fused main
    {
        dim3 grid(NC / CPB, NB / NPB);   // (64, 8) = 512 blocks
        sc_main_kernel<<<grid, 256>>>(A, (float*)d_out);
    }
}

// round 16
// speedup vs baseline: 1.2665x; 1.0448x over previous
#include <cuda_runtime.h>

// ---------------------------------------------------------------------------
// SymmetricContraction: out[b,c,m] = cubic polynomial in A[b,c,0..8]
// Launch 1 (prep):  S[c][t][m] = sum_k Usym[t][m][k] * w_k[c]  (g_S)
// Launch 2 (main):  fused f32x2, NBT=2, CPB=2, NPB=128, 128 thr.
//   smem 30.8KB -> 7 blocks/SM (28 warps); grid 1024 -> ~1% wave imbalance.
//   4 warps = 2 channels x 2 node-quarters.
// ---------------------------------------------------------------------------

#define NC 128
#define NB 2048
#define NI 9
#define NT 219
#define ROWP 12
#define TBLW (NT * ROWP)          // 2628 floats per channel table
#define CPB 2                     // channels per block
#define NPB 128                   // nodes per block
#define BLKT 128                  // threads per main block
#define TS 19                     // tile row stride (2*9+1, odd)
#define SM_FLOATS (CPB * TBLW + NPB * TS)     // 5256 + 2432 = 7688
                                              // = 30752 B (< 48KB default)

#define NJOBS (NT * 9)
#define RPB 2
#define PREP_BLOCKS ((NJOBS + RPB - 1) / RPB)  // 986

static __device__ float g_S[NC * TBLW];

typedef unsigned long long u64;

__device__ __forceinline__ u64 dup2(float x) {
    u64 r; unsigned xi = __float_as_uint(x);
    asm("mov.b64 %0, {%1, %1};" : "=l"(r) : "r"(xi));
    return r;
}
__device__ __forceinline__ u64 fma2(u64 a, u64 b, u64 c) {
    u64 r;
    asm("fma.rn.f32x2 %0, %1, %2, %3;" : "=l"(r) : "l"(a), "l"(b), "l"(c));
    return r;
}
__device__ __forceinline__ void unpack2(u64 v, float& lo, float& hi) {
    unsigned l_, h_;
    asm("mov.b64 {%0, %1}, %2;" : "=r"(l_), "=r"(h_) : "l"(v));
    lo = __uint_as_float(l_); hi = __uint_as_float(h_);
}

// ---------------------------------------------------------------------------
// Launch 1: prep (verified, unchanged)
// ---------------------------------------------------------------------------
__global__ __launch_bounds__(256) void prep_kernel(
    const float* __restrict__ Us1, const float* __restrict__ Up1, const float* __restrict__ Ud1,
    const float* __restrict__ Us2, const float* __restrict__ Up2, const float* __restrict__ Ud2,
    const float* __restrict__ Us3, const float* __restrict__ Up3, const float* __restrict__ Ud3,
    const float* __restrict__ ws1, const float* __restrict__ ws2, const float* __restrict__ ws3,
    const float* __restrict__ wp1, const float* __restrict__ wp2, const float* __restrict__ wp3,
    const float* __restrict__ wd1, const float* __restrict__ wd2, const float* __restrict__ wd3)
{
    __shared__ float sU[RPB][10];
    int r0 = blockIdx.x * RPB;
    int tid = threadIdx.x;

    if (tid < RPB * 10) {
        int rl = tid / 10, k = tid % 10;
        int r = r0 + rl;
        float usym = 0.f;
        if (r < NJOBS) {
            int t = r / 9, m = r - t * 9;
            if (t < 9) {
                if (k == 0) {
                    int i = t;
                    if (m == 0)      usym = Us1[i];
                    else if (m < 4)  usym = Up1[(m - 1) * 9 + i];
                    else             usym = Ud1[(m - 4) * 9 + i];
                }
            } else if (t < 54) {
                int tp = t - 9;
                int rem = tp, i = 0, j = 0;
                for (i = 0; i < 9; i++) { int cnt = 9 - i; if (rem < cnt) { j = i + rem; break; } rem -= cnt; }
                float inv = (i == j) ? 0.5f : 1.0f;
                int K; const float* U; int mm;
                if (m == 0)      { K = 2; U = Us2; mm = 0; }
                else if (m < 4)  { K = 3; U = Up2; mm = m - 1; }
                else             { K = 4; U = Ud2; mm = m - 4; }
                if (k < K)
                    usym = (U[((mm * 9 + i) * 9 + j) * K + k] +
                            U[((mm * 9 + j) * 9 + i) * K + k]) * inv;
            } else {
                int tp = t - 54;
                int rem = tp, i = 0, j = 0, l = 0;
                for (i = 0; i < 9; i++) { int cnt = (9 - i) * (10 - i) / 2; if (rem < cnt) break; rem -= cnt; }
                for (j = i; j < 9; j++) { int cnt = 9 - j; if (rem < cnt) { l = j + rem; break; } rem -= cnt; }
                float inv;
                if (i == j && j == l)                 inv = 1.0f / 6.0f;
                else if (i == j || j == l || i == l)  inv = 0.5f;
                else                                  inv = 1.0f;
                int K; const float* U; int mm;
                if (m == 0)      { K = 5;  U = Us3; mm = 0; }
                else if (m < 4)  { K = 8;  U = Up3; mm = m - 1; }
                else             { K = 10; U = Ud3; mm = m - 4; }
                if (k < K) {
                    int P0[6] = { i,i,j,j,l,l }, P1[6] = { j,l,i,l,i,j }, P2[6] = { l,j,l,i,j,i };
                    float s = 0.f;
#pragma unroll
                    for (int p = 0; p < 6; p++)
                        s += U[(((mm * 9 + P0[p]) * 9 + P1[p]) * 9 + P2[p]) * K + k];
                    usym = s * inv;
                }
            }
        }
        sU[rl][k] = usym;
    }
    __syncthreads();

    {
        int rl = tid >> 7;
        int c  = tid & 127;
        int r = r0 + rl;
        if (r >= NJOBS) return;
        int t = r / 9, m = r - t * 9;

        const float* w; int K;
        if (t < 9) {
            K = 1;
            w = (m == 0) ? ws1 : (m < 4) ? wp1 : wd1;
        } else if (t < 54) {
            if (m == 0)      { K = 2; w = ws2; }
            else if (m < 4)  { K = 3; w = wp2; }
            else             { K = 4; w = wd2; }
        } else {
            if (m == 0)      { K = 5;  w = ws3; }
            else if (m < 4)  { K = 8;  w = wp3; }
            else             { K = 10; w = wd3; }
        }

        float s = 0.f;
        for (int k = 0; k < K; k++)
            s = fmaf(sU[rl][k], w[k * NC + c], s);

        float* dst = g_S + c * TBLW + t * ROWP;
        dst[m] = s;
        if (m < 3) dst[9 + m] = 0.f;   // row[9] pad is load-bearing for f32x2
    }
}

// ---------------------------------------------------------------------------
// Launch 2: fused main (CPB=2, NPB=128, 128 thr -> 7 blocks/SM, 1024 blocks)
// ---------------------------------------------------------------------------
__device__ __forceinline__ void fmarow(u64 acc0[5], u64 acc1[5],
                                       const float* __restrict__ row,
                                       float m0, float m1)
{
    u64 d0 = dup2(m0), d1 = dup2(m1);
    ulonglong2 ra = *reinterpret_cast<const ulonglong2*>(row);       // (r0,r1)(r2,r3)
    ulonglong2 rb = *reinterpret_cast<const ulonglong2*>(row + 4);   // (r4,r5)(r6,r7)
    u64 rc = *reinterpret_cast<const u64*>(row + 8);                 // (r8, pad)
    acc0[0] = fma2(ra.x, d0, acc0[0]);  acc1[0] = fma2(ra.x, d1, acc1[0]);
    acc0[1] = fma2(ra.y, d0, acc0[1]);  acc1[1] = fma2(ra.y, d1, acc1[1]);
    acc0[2] = fma2(rb.x, d0, acc0[2]);  acc1[2] = fma2(rb.x, d1, acc1[2]);
    acc0[3] = fma2(rb.y, d0, acc0[3]);  acc1[3] = fma2(rb.y, d1, acc1[3]);
    acc0[4] = fma2(rc,   d0, acc0[4]);  acc1[4] = fma2(rc,   d1, acc1[4]);
}

__global__ __launch_bounds__(BLKT, 8) void sc_main_kernel(
    const float* __restrict__ A, float* __restrict__ out)
{
    __shared__ __align__(16) float smem[SM_FLOATS];
    float* sT = smem;                    // [CPB][TBLW]
    float* sA = smem + CPB * TBLW;       // [NPB][TS], reused for output

    int c0 = blockIdx.x * CPB;
    int b0 = blockIdx.y * NPB;
    int tid = threadIdx.x;
    int w = tid >> 5, lane = tid & 31;
    int ch = w & 1;                      // channel within block
    int quad = w >> 1;                   // node quarter (0..1)

    // ---- fill tables: flat float4 copy (deep MLP)
    {
        const float4* src4 = reinterpret_cast<const float4*>(g_S + c0 * TBLW);
        float4* dst4 = reinterpret_cast<float4*>(sT);
#pragma unroll 4
        for (int v = tid; v < (CPB * TBLW) / 4; v += BLKT)
            dst4[v] = src4[v];
    }

    // ---- fill A tile: 128 runs of 18 contiguous floats
#pragma unroll 4
    for (int v = tid; v < NPB * (CPB * NI); v += BLKT) {
        int b = v / (CPB * NI), q = v - b * (CPB * NI);
        sA[b * TS + q] = A[(b0 + b) * (NC * NI) + c0 * NI + q];
    }
    __syncthreads();

    // ---- per-thread a vectors (stride-19 LDS, conflict-free)
    int row0 = quad * 64 + lane;         // nodes row0 and row0+32
    float a0[9], a1[9];
    {
        const float* p0 = sA + row0 * TS + ch * NI;
        const float* p1 = sA + (row0 + 32) * TS + ch * NI;
#pragma unroll
        for (int i = 0; i < 9; i++) { a0[i] = p0[i]; a1[i] = p1[i]; }
    }
    __syncthreads();   // tile reads complete before epilogue overwrite

    const float* tbl = sT + ch * TBLW;

    u64 acc0[5], acc1[5];
#pragma unroll
    for (int q = 0; q < 5; q++) { acc0[q] = 0ull; acc1[q] = 0ull; }

    // ---- degree 1
#pragma unroll
    for (int i = 0; i < 9; i++)
        fmarow(acc0, acc1, tbl + i * ROWP, a0[i], a1[i]);

    // ---- degree 2 + 3
    int trow = 54;
#pragma unroll
    for (int i = 0; i < 9; i++) {
#pragma unroll
        for (int j = i; j < 9; j++) {
            int pidx = i * 9 - (i * (i - 1)) / 2 + (j - i);
            float p0 = a0[i] * a0[j];
            float p1 = a1[i] * a1[j];
            fmarow(acc0, acc1, tbl + (9 + pidx) * ROWP, p0, p1);
#pragma unroll
            for (int l = j; l < 9; l++) {
                fmarow(acc0, acc1, tbl + trow * ROWP, p0 * a0[l], p1 * a1[l]);
                trow++;
            }
        }
    }

    // ---- stage results into tile, then coalesced flush
    {
        float* o0 = sA + row0 * TS + ch * NI;
        float* o1 = sA + (row0 + 32) * TS + ch * NI;
#pragma unroll
        for (int q = 0; q < 4; q++) {
            float lo, hi;
            unpack2(acc0[q], lo, hi); o0[2 * q] = lo; o0[2 * q + 1] = hi;
            unpack2(acc1[q], lo, hi); o1[2 * q] = lo; o1[2 * q + 1] = hi;
        }
        float lo, hi;
        unpack2(acc0[4], lo, hi); o0[8] = lo;
        unpack2(acc1[4], lo, hi); o1[8] = lo;
    }
    __syncthreads();

#pragma unroll 4
    for (int v = tid; v < NPB * (CPB * NI); v += BLKT) {
        int b = v / (CPB * NI), q = v - b * (CPB * NI);
        out[(b0 + b) * (NC * NI) + c0 * NI + q] = sA[b * TS + q];
    }
}

// ---------------------------------------------------------------------------
// Launch
// ---------------------------------------------------------------------------
extern "C" void kernel_launch(void* const* d_in, const int* in_sizes, int n_in,
                              void* d_out, int out_size)
{
    const float* A = nullptr;
    const float* U[3][3] = {};
    const float* W[3][3] = {};

    int typeorder[3] = { 0, 1, 2 };
    int to_n = 0;
    int w1_idx[3]; int w1_n = 0;

    for (int idx = 0; idx < n_in; idx++) {
        int s = in_sizes[idx];
        const float* p = (const float*)d_in[idx];
        switch (s) {
            case NB * NC * NI: A = p; break;
            case 9:     U[0][0] = p; break;
            case 162:   U[0][1] = p; break;
            case 3645:  U[0][2] = p; break;
            case 27:    U[1][0] = p; break;
            case 729:   U[1][1] = p; break;
            case 17496: U[1][2] = p; break;
            case 45:    U[2][0] = p; break;
            case 1620:  U[2][1] = p; break;
            case 36450: U[2][2] = p; break;
            case 256:   W[0][1] = p; if (to_n < 3) typeorder[to_n++] = 0; break;
            case 384:   W[1][1] = p; if (to_n < 3) typeorder[to_n++] = 1; break;
            case 512:   W[2][1] = p; if (to_n < 3) typeorder[to_n++] = 2; break;
            case 640:   W[0][2] = p; break;
            case 1024:  W[1][2] = p; break;
            case 1280:  W[2][2] = p; break;
            case 128:   if (w1_n < 3) w1_idx[w1_n++] = idx; break;
            default: break;
        }
    }
    for (int q = 0; q < 3 && q < w1_n; q++)
        W[typeorder[q]][0] = (const float*)d_in[w1_idx[q]];

    // Launch 1: prep
    prep_kernel<<<PREP_BLOCKS, 256>>>(
        U[0][0], U[1][0], U[2][0],
        U[0][1], U[1][1], U[2][1],
        U[0][2], U[1][2], U[2][2],
        W[0][0], W[0][1], W[0][2],
        W[1][0], W[1][1], W[1][2],
        W[2][0], W[2][1], W[2][2]);

    // Launch 2: fused main
    {
        dim3 grid(NC / CPB, NB / NPB);   // (64, 16) = 1024 blocks
        sc_main_kernel<<<grid, BLKT>>>(A, (float*)d_out);
    }
}